// round 1
// baseline (speedup 1.0000x reference)
#include <cuda_runtime.h>
#include <math.h>

#define N_FEAT 7
#define FUZZ   2187
#define MID    512
#define NCLS   10
#define BATCH  4096
#define T21    21          // N_FEAT * 3 distinct u values
#define NCHUNK 81          // k-chunks for wei reduction
#define CHUNK_K 27         // k per chunk (81*27 = 2187)
#define COLT   9           // column tiles of 256 (9*256 >= 2187)
#define WCH    16          // j-chunks for W23 partials

// ---- device scratch (no allocations allowed) ----
__device__ float g_partialS[NCHUNK * T21 * FUZZ];  // ~14.9 MB
__device__ float g_S[T21 * FUZZ];
__device__ float g_rowS[T21];
__device__ float g_T1[T21 * MID];
__device__ float g_r1[MID];
__device__ float g_T3[NCLS * T21];
__device__ float g_r3[NCLS];
__device__ float g_c3[NCLS];
__device__ float g_partW[WCH * NCLS * MID];
__device__ float g_W23[NCLS * MID];

// ============================================================
// Stage 1: partial S[(f,m), j] over k-chunks  +  W23 partials
// ============================================================
__global__ void k_stage1(const float* __restrict__ wei,
                         const float* __restrict__ W2,
                         const float* __restrict__ W3) {
    int b   = blockIdx.x;
    int tid = threadIdx.x;

    if (b < NCHUNK * COLT) {
        // ---- S partial: sum wei rows into 21 buckets per column ----
        int colTile = b % COLT;
        int chunk   = b / COLT;
        int j  = colTile * 256 + tid;
        bool ok = (j < FUZZ);
        int jj = ok ? j : 0;

        float acc[T21];
#pragma unroll
        for (int t = 0; t < T21; t++) acc[t] = 0.f;

        int k0 = chunk * CHUNK_K;
#pragma unroll 3
        for (int kk = 0; kk < CHUNK_K; kk++) {
            int k = k0 + kk;
            const float* rowp = wei + (size_t)(k * 7) * FUZZ + jj;
            const int P[7] = {729, 243, 81, 27, 9, 3, 1};
#pragma unroll
            for (int f = 0; f < 7; f++) {
                float v = __ldg(rowp + f * FUZZ);
                int m = (k / P[f]) % 3;
                acc[f * 3 + 0] += (m == 0) ? v : 0.f;
                acc[f * 3 + 1] += (m == 1) ? v : 0.f;
                acc[f * 3 + 2] += (m == 2) ? v : 0.f;
            }
        }
        if (ok) {
            float* dst = g_partialS + (size_t)chunk * (T21 * FUZZ) + j;
#pragma unroll
            for (int t = 0; t < T21; t++) dst[t * FUZZ] = acc[t];
        }
    } else {
        // ---- W23 partial: W23[n,i] = sum_j W3[n,j] * W2[j,i] ----
        int b2    = b - NCHUNK * COLT;
        int itile = b2 & 1;
        int chunk = b2 >> 1;
        int i  = itile * 256 + tid;
        int j0 = chunk * 137;
        int j1 = min(FUZZ, j0 + 137);

        float acc[NCLS];
#pragma unroll
        for (int n = 0; n < NCLS; n++) acc[n] = 0.f;

        for (int j = j0; j < j1; j++) {
            float w2 = __ldg(W2 + j * MID + i);
#pragma unroll
            for (int n = 0; n < NCLS; n++)
                acc[n] += __ldg(W3 + n * FUZZ + j) * w2;
        }
#pragma unroll
        for (int n = 0; n < NCLS; n++)
            g_partW[chunk * (NCLS * MID) + n * MID + i] = acc[n];
    }
}

// ============================================================
// Stage 2: reduce S partials (fixed order -> deterministic)
// ============================================================
__global__ void k_reduceS() {
    int idx = blockIdx.x * 256 + threadIdx.x;
    if (idx < T21 * FUZZ) {
        float s = 0.f;
#pragma unroll 9
        for (int c = 0; c < NCHUNK; c++)
            s += g_partialS[(size_t)c * (T21 * FUZZ) + idx];
        g_S[idx] = s;
    }
}

// ============================================================
// Stage 3: T1 = S@W1^T, r1 = rowsum(W1), T3/r3/c3, rowS, W23 reduce
// ============================================================
__global__ void k_stage3(const float* __restrict__ W1,
                         const float* __restrict__ W3,
                         const float* __restrict__ b2) {
    __shared__ float sm[23 * 8];
    int b    = blockIdx.x;
    int tid  = threadIdx.x;
    int lane = tid & 31;
    int warp = tid >> 5;

    if (b < MID) {
        // T1[t][i] and r1[i] for i = b
        int i = b;
        float acc[22];
#pragma unroll
        for (int t = 0; t < 22; t++) acc[t] = 0.f;
        for (int j = tid; j < FUZZ; j += 256) {
            float w = __ldg(W1 + i * FUZZ + j);
#pragma unroll
            for (int t = 0; t < T21; t++) acc[t] += w * g_S[t * FUZZ + j];
            acc[21] += w;
        }
#pragma unroll
        for (int t = 0; t < 22; t++) {
            for (int off = 16; off; off >>= 1)
                acc[t] += __shfl_down_sync(0xffffffffu, acc[t], off);
            if (lane == 0) sm[t * 8 + warp] = acc[t];
        }
        __syncthreads();
        if (tid < 22) {
            float s = 0.f;
#pragma unroll
            for (int w = 0; w < 8; w++) s += sm[tid * 8 + w];
            if (tid < T21) g_T1[tid * MID + i] = s;
            else           g_r1[i] = s;
        }
    } else if (b < MID + NCLS) {
        // T3[n][t], r3[n], c3[n] for n = b - MID
        int n = b - MID;
        float acc[23];
#pragma unroll
        for (int t = 0; t < 23; t++) acc[t] = 0.f;
        for (int j = tid; j < FUZZ; j += 256) {
            float w3 = __ldg(W3 + n * FUZZ + j);
#pragma unroll
            for (int t = 0; t < T21; t++) acc[t] += w3 * g_S[t * FUZZ + j];
            acc[21] += w3;
            acc[22] += w3 * __ldg(b2 + j);
        }
#pragma unroll
        for (int t = 0; t < 23; t++) {
            for (int off = 16; off; off >>= 1)
                acc[t] += __shfl_down_sync(0xffffffffu, acc[t], off);
            if (lane == 0) sm[t * 8 + warp] = acc[t];
        }
        __syncthreads();
        if (tid < 23) {
            float s = 0.f;
#pragma unroll
            for (int w = 0; w < 8; w++) s += sm[tid * 8 + w];
            if (tid < T21)       g_T3[n * T21 + tid] = s;
            else if (tid == 21)  g_r3[n] = s;
            else                 g_c3[n] = s;
        }
    } else if (b < MID + NCLS + T21) {
        // rowS[t] = sum_j S[t][j]
        int t = b - MID - NCLS;
        float s = 0.f;
        for (int j = tid; j < FUZZ; j += 256) s += g_S[t * FUZZ + j];
        for (int off = 16; off; off >>= 1)
            s += __shfl_down_sync(0xffffffffu, s, off);
        if (lane == 0) sm[warp] = s;
        __syncthreads();
        if (tid == 0) {
            float tot = 0.f;
#pragma unroll
            for (int w = 0; w < 8; w++) tot += sm[w];
            g_rowS[t] = tot;
        }
    } else {
        // W23 reduce over WCH chunks
        for (int e = tid; e < NCLS * MID; e += 256) {
            float s = 0.f;
#pragma unroll
            for (int c = 0; c < WCH; c++) s += g_partW[c * (NCLS * MID) + e];
            g_W23[e] = s;
        }
    }
}

// ============================================================
// Stage 4: per-batch-row fused pipeline (8 rows per block)
// ============================================================
__global__ void __launch_bounds__(512) k_main(
        const float* __restrict__ x,  const float* __restrict__ cc,
        const float* __restrict__ bb, const float* __restrict__ bais,
        const float* __restrict__ b1, const float* __restrict__ b3,
        float* __restrict__ out) {
    __shared__ float sT1[T21 * MID];   // 43008 B
    __shared__ float sh1[MID];
    __shared__ float su[T21];
    __shared__ float srowS[T21];

    int tid  = threadIdx.x;
    int lane = tid & 31;
    int warp = tid >> 5;

    for (int e = tid; e < T21 * MID; e += 512) sT1[e] = g_T1[e];
    if (tid < T21) srowS[tid] = g_rowS[tid];

    float r1v = g_r1[tid];
    float b1v = b1[tid];
    float bv_ = bais[0];

    float w23r[16];
    float t3v = 0.f, r3v = 0.f, c3v = 0.f, b3v = 0.f;
    if (warp < NCLS) {
#pragma unroll
        for (int it = 0; it < 16; it++)
            w23r[it] = g_W23[warp * MID + it * 32 + lane];
        if (lane < T21) t3v = g_T3[warp * T21 + lane];
        r3v = g_r3[warp]; c3v = g_c3[warp]; b3v = b3[warp];
    }
    __syncthreads();

#pragma unroll 1
    for (int r = 0; r < 8; r++) {
        int row = blockIdx.x * 8 + r;

        if (tid < T21) {
            int f = tid / 3;
            float d  = x[row * 7 + f] - cc[tid];   // cc is (7,3) row-major
            float bw = bb[tid];
            su[tid] = expf(-d * d / (bw * bw));
        }
        __syncthreads();

        float rs = (float)FUZZ * bv_;
#pragma unroll
        for (int t = 0; t < T21; t++) rs += su[t] * srowS[t];
        float inv = 1.0f / rs;

        float acc = bv_ * r1v;
#pragma unroll
        for (int t = 0; t < T21; t++) acc += su[t] * sT1[t * MID + tid];
        float h1 = acc * inv + b1v;
        sh1[tid] = h1;
        __syncthreads();

        if (warp < NCLS) {
            float p = 0.f;
#pragma unroll
            for (int it = 0; it < 16; it++)
                p += sh1[it * 32 + lane] * w23r[it];
            if (lane < T21) p += su[lane] * t3v * inv;   // a_mean @ W3^T part
            for (int off = 16; off; off >>= 1)
                p += __shfl_down_sync(0xffffffffu, p, off);
            if (lane == 0) {
                float h3 = p + bv_ * r3v * inv + c3v + b3v;
                out[row * NCLS + warp] = (h3 >= 0.f) ? h3 : 0.2f * h3;
            }
        }
        __syncthreads();
    }
}

// ============================================================
extern "C" void kernel_launch(void* const* d_in, const int* in_sizes, int n_in,
                              void* d_out, int out_size) {
    const float* x    = (const float*)d_in[0];
    const float* c    = (const float*)d_in[1];
    const float* b    = (const float*)d_in[2];
    const float* wei  = (const float*)d_in[3];
    const float* bais = (const float*)d_in[4];
    const float* W1   = (const float*)d_in[5];
    const float* b1   = (const float*)d_in[6];
    const float* W2   = (const float*)d_in[7];
    const float* b2   = (const float*)d_in[8];
    const float* W3   = (const float*)d_in[9];
    const float* b3   = (const float*)d_in[10];
    float* out = (float*)d_out;

    k_stage1<<<NCHUNK * COLT + 2 * WCH, 256>>>(wei, W2, W3);
    k_reduceS<<<(T21 * FUZZ + 255) / 256, 256>>>();
    k_stage3<<<MID + NCLS + T21 + 1, 256>>>(W1, W3, b2);
    k_main<<<BATCH / 8, 512>>>(x, c, b, bais, b1, b3, out);
}